// round 1
// baseline (speedup 1.0000x reference)
#include <cuda_runtime.h>
#include <cstdint>

#define BB 1024
#define TT 256
#define NN 64

// Packed transition matrix: g_P[j*32 + l] = pack(P[j][l], P[j][l+32])
__device__ unsigned long long g_P[64 * 32];
__device__ float g_Ps[NN];   // exp(strans - lse(strans))
__device__ float g_Pe[NN];   // exp(etrans - lse(etrans))
__device__ int   g_mask_dtype;   // 0 = uint8/bool, 1 = int32, 2 = float32
__device__ float g_logZ[BB];

__device__ __forceinline__ unsigned long long pack2(float lo, float hi) {
    return ((unsigned long long)__float_as_uint(hi) << 32) |
           (unsigned long long)__float_as_uint(lo);
}

// ---------------------------------------------------------------------------
// Prep: normalize transitions into probability space, detect mask dtype.
// ---------------------------------------------------------------------------
__global__ void prep_kernel(const float* __restrict__ trans,
                            const float* __restrict__ strans,
                            const float* __restrict__ etrans,
                            const void*  __restrict__ mask)
{
    int tid = threadIdx.x;  // 64 threads

    if (tid == 0) {
        // mask dtype detection using row 0: true-count in [T/2, T] = [128,256].
        // uint8 bytes of row 0 sum to len0 iff dtype is 1-byte bool.
        const unsigned char* mu = (const unsigned char*)mask;
        int s8 = 0;
        for (int i = 0; i < 256; i++) s8 += mu[i];
        int dt;
        if (s8 >= 128 && s8 <= 256) {
            dt = 0;
        } else {
            const int* mi = (const int*)mask;   // 256 ints = 1024 bytes, in-bounds
            long long s32 = 0;
            for (int i = 0; i < 256; i++) s32 += mi[i];
            dt = (s32 >= 128 && s32 <= 256) ? 1 : 2;
        }
        g_mask_dtype = dt;

        // strans
        float mx = -1e30f;
        for (int k = 0; k < NN; k++) mx = fmaxf(mx, strans[k]);
        float s = 0.f;
        for (int k = 0; k < NN; k++) s += __expf(strans[k] - mx);
        float inv = 1.f / s;
        for (int k = 0; k < NN; k++) g_Ps[k] = __expf(strans[k] - mx) * inv;
    }
    if (tid == 1) {
        float mx = -1e30f;
        for (int k = 0; k < NN; k++) mx = fmaxf(mx, etrans[k]);
        float s = 0.f;
        for (int k = 0; k < NN; k++) s += __expf(etrans[k] - mx);
        float inv = 1.f / s;
        for (int k = 0; k < NN; k++) g_Pe[k] = __expf(etrans[k] - mx) * inv;
    }

    // Row-normalized transition probabilities: P[j][k] = exp(trans_n[j][k])
    int j = tid;
    float mx = -1e30f;
    for (int k = 0; k < NN; k++) mx = fmaxf(mx, trans[j * NN + k]);
    float s = 0.f;
    for (int k = 0; k < NN; k++) s += __expf(trans[j * NN + k] - mx);
    float inv = 1.f / s;
    for (int l = 0; l < 32; l++) {
        float lo = __expf(trans[j * NN + l]      - mx) * inv;
        float hi = __expf(trans[j * NN + l + 32] - mx) * inv;
        g_P[j * 32 + l] = pack2(lo, hi);
    }
}

// ---------------------------------------------------------------------------
// Main: warp-per-batch exp-domain forward recursion.
// Lane l owns labels {l, l+32}. P held in 128 registers as f32x2 pairs.
// ---------------------------------------------------------------------------
__global__ void __launch_bounds__(128, 1)
crf_kernel(const float* __restrict__ emit, const void* __restrict__ mask)
{
    const int lane = threadIdx.x & 31;
    const int wib  = threadIdx.x >> 5;              // warp in block (0..3)
    const int b    = blockIdx.x * 4 + wib;          // batch index (0..1023)

    // Load P into registers (coalesced, L2-resident: 16KB total)
    unsigned long long p[64];
#pragma unroll
    for (int j = 0; j < 64; j++) p[j] = g_P[j * 32 + lane];

    // Sequence length from monotone mask
    const int dt = g_mask_dtype;
    int len = 0;
    if (dt == 0) {
        const unsigned* m = (const unsigned*)mask;  // bytes are exactly 0x00/0x01
        len = __popc(m[b * 64 + lane]) + __popc(m[b * 64 + 32 + lane]);
    } else if (dt == 1) {
        const int* m = (const int*)mask + (size_t)b * TT;
        for (int t = lane; t < TT; t += 32) len += (m[t] != 0);
    } else {
        const float* m = (const float*)mask + (size_t)b * TT;
        for (int t = lane; t < TT; t += 32) len += (m[t] != 0.f);
    }
#pragma unroll
    for (int o = 16; o; o >>= 1) len += __shfl_xor_sync(0xffffffffu, len, o);

    const float* eb = emit + (size_t)b * TT * NN;

    // alpha0 = strans_n + emit[0]  ->  A0 = Ps * exp(emit0)
    float ax = g_Ps[lane]      * __expf(eb[lane]);
    float ay = g_Ps[lane + 32] * __expf(eb[lane + 32]);
    float C  = 0.f;

    // Broadcast buffer: duplicated pairs (a_j, a_j), double-buffered so a
    // single __syncwarp per step suffices.
    __shared__ unsigned long long sh[4][2][64];

    int tf = (1 < len) ? 1 : 0;
    float pex = eb[tf * NN + lane];
    float pey = eb[tf * NN + lane + 32];

    for (int t = 1; t < len; t++) {
        const int buf = t & 1;
        *(float2*)&sh[wib][buf][lane]      = make_float2(ax, ax);
        *(float2*)&sh[wib][buf][lane + 32] = make_float2(ay, ay);

        // software-pipelined emit prefetch (hides DRAM latency)
        const float ex = pex, ey = pey;
        const int t2 = (t + 1 < len) ? (t + 1) : t;
        pex = eb[t2 * NN + lane];
        pey = eb[t2 * NN + lane + 32];

        __syncwarp();

        const unsigned long long* sa = sh[wib][buf];
        unsigned long long acc0 = 0ull, acc1 = 0ull;   // (0.f, 0.f) packed
#pragma unroll
        for (int j = 0; j < 64; j += 2) {
            asm volatile("fma.rn.f32x2 %0, %1, %2, %0;"
                         : "+l"(acc0) : "l"(sa[j]),     "l"(p[j]));
            asm volatile("fma.rn.f32x2 %0, %1, %2, %0;"
                         : "+l"(acc1) : "l"(sa[j + 1]), "l"(p[j + 1]));
        }
        asm volatile("add.rn.f32x2 %0, %0, %1;" : "+l"(acc0) : "l"(acc1));
        float sx = __uint_as_float((unsigned)acc0);
        float sy = __uint_as_float((unsigned)(acc0 >> 32));

        ax = sx * __expf(ex);
        ay = sy * __expf(ey);

        // Renormalize every 8 steps: worst-case growth e^{8*max|emit|} << FLT_MAX
        if ((t & 7) == 0) {
            float s = ax + ay;
#pragma unroll
            for (int o = 16; o; o >>= 1) s += __shfl_xor_sync(0xffffffffu, s, o);
            C += __logf(s);
            float inv = __fdividef(1.f, s);
            ax *= inv;
            ay *= inv;
        }
    }

    // logZ_b = C + log(sum_k A_k * exp(etrans_n_k))
    float z = ax * g_Pe[lane] + ay * g_Pe[lane + 32];
#pragma unroll
    for (int o = 16; o; o >>= 1) z += __shfl_xor_sync(0xffffffffu, z, o);
    if (lane == 0) g_logZ[b] = C + __logf(z);
}

// ---------------------------------------------------------------------------
// Deterministic batch reduction (no float atomics).
// ---------------------------------------------------------------------------
__global__ void reduce_kernel(float* __restrict__ out)
{
    __shared__ float s[256];
    int tid = threadIdx.x;
    float v = 0.f;
    for (int i = tid; i < BB; i += 256) v += g_logZ[i];
    s[tid] = v;
    __syncthreads();
    for (int o = 128; o; o >>= 1) {
        if (tid < o) s[tid] += s[tid + o];
        __syncthreads();
    }
    if (tid == 0) out[0] = s[0];
}

extern "C" void kernel_launch(void* const* d_in, const int* in_sizes, int n_in,
                              void* d_out, int out_size)
{
    // Resolve inputs by size (defensive), keeping dict order for the two
    // size-64 vectors (strans before etrans).
    const float* emit   = nullptr;
    const float* trans  = nullptr;
    const float* strans = nullptr;
    const float* etrans = nullptr;
    const void*  mask   = nullptr;
    for (int i = 0; i < n_in; i++) {
        long long sz = in_sizes[i];
        if (sz == (long long)BB * TT * NN)      emit  = (const float*)d_in[i];
        else if (sz == NN * NN)                 trans = (const float*)d_in[i];
        else if (sz == (long long)BB * TT)      mask  = d_in[i];
        else if (sz == NN) {
            if (!strans) strans = (const float*)d_in[i];
            else         etrans = (const float*)d_in[i];
        }
    }

    prep_kernel<<<1, 64>>>(trans, strans, etrans, mask);
    crf_kernel<<<256, 128>>>(emit, mask);
    reduce_kernel<<<1, 256>>>((float*)d_out);
}

// round 2
// speedup vs baseline: 1.1916x; 1.1916x over previous
#include <cuda_runtime.h>
#include <cstdint>

#define BB 1024
#define TT 256
#define NN 64

// Packed transition matrix: g_P[j*32 + l] = pack(P[j][l], P[j][l+32])
__device__ unsigned long long g_P[64 * 32];
__device__ float g_Ps[NN];      // exp(strans - lse(strans))
__device__ float g_Pe[NN];      // exp(etrans - lse(etrans))
__device__ int   g_mask_dtype;  // 0 = uint8/bool, 1 = int32, 2 = float32
__device__ float g_logZ[BB];

__device__ __forceinline__ unsigned long long pack2(float lo, float hi) {
    return ((unsigned long long)__float_as_uint(hi) << 32) |
           (unsigned long long)__float_as_uint(lo);
}

__device__ __forceinline__ float warp_max(float v) {
#pragma unroll
    for (int o = 16; o; o >>= 1) v = fmaxf(v, __shfl_xor_sync(0xffffffffu, v, o));
    return v;
}
__device__ __forceinline__ float warp_sum(float v) {
#pragma unroll
    for (int o = 16; o; o >>= 1) v += __shfl_xor_sync(0xffffffffu, v, o);
    return v;
}
__device__ __forceinline__ int warp_sum_i(int v) {
#pragma unroll
    for (int o = 16; o; o >>= 1) v += __shfl_xor_sync(0xffffffffu, v, o);
    return v;
}

// ---------------------------------------------------------------------------
// Prep: fully parallel. grid=64, block=64.
//   warp0 of block j : normalize trans row j
//   warp1 of block 0 : strans;  block 1 : etrans;  block 2 : mask dtype detect
// ---------------------------------------------------------------------------
__global__ void prep_kernel(const float* __restrict__ trans,
                            const float* __restrict__ strans,
                            const float* __restrict__ etrans,
                            const void*  __restrict__ mask)
{
    const int j    = blockIdx.x;
    const int w    = threadIdx.x >> 5;
    const int lane = threadIdx.x & 31;

    if (w == 0) {
        // Row-normalized transition probabilities: P[j][k] = exp(trans_n[j][k])
        float a = trans[j * NN + lane];
        float b = trans[j * NN + lane + 32];
        float mx = warp_max(fmaxf(a, b));
        float ea = __expf(a - mx), eb = __expf(b - mx);
        float inv = __fdividef(1.f, warp_sum(ea + eb));
        g_P[j * 32 + lane] = pack2(ea * inv, eb * inv);
    } else if (j == 0) {
        float a = strans[lane], b = strans[lane + 32];
        float mx = warp_max(fmaxf(a, b));
        float ea = __expf(a - mx), eb = __expf(b - mx);
        float inv = __fdividef(1.f, warp_sum(ea + eb));
        g_Ps[lane] = ea * inv;  g_Ps[lane + 32] = eb * inv;
    } else if (j == 1) {
        float a = etrans[lane], b = etrans[lane + 32];
        float mx = warp_max(fmaxf(a, b));
        float ea = __expf(a - mx), eb = __expf(b - mx);
        float inv = __fdividef(1.f, warp_sum(ea + eb));
        g_Pe[lane] = ea * inv;  g_Pe[lane + 32] = eb * inv;
    } else if (j == 2) {
        // mask dtype detection on row 0: lens >= T/2, so row-0 true count in
        // [128,256] and the first 128 elements are all true (prefix mask).
        const unsigned* mu = (const unsigned*)mask;   // first 256 bytes
        int s8 = warp_sum_i(__popc(mu[lane]) + __popc(mu[lane + 32]));
        int dt;
        if (s8 >= 128 && s8 <= 256) {
            dt = 0;                                    // 1-byte bool (0/1 bytes)
        } else {
            const int* mi = (const int*)mask;          // first 256 ints in-bounds
            long long s = 0;
            for (int i = lane; i < 256; i += 32) s += mi[i];
#pragma unroll
            for (int o = 16; o; o >>= 1) s += __shfl_xor_sync(0xffffffffu, s, o);
            dt = (s >= 128 && s <= 256) ? 1 : 2;       // int32 vs float32
        }
        if (lane == 0) g_mask_dtype = dt;
    }
}

// ---------------------------------------------------------------------------
// Main: warp-per-batch exp-domain forward recursion.
// Lane l owns labels {l, l+32}. P held in 128 registers as f32x2 pairs.
// Per step: LDS.128 broadcast of duplicated alpha pairs, 64 packed FMAs on
// 4 independent accumulator chains (16 deep each).
// ---------------------------------------------------------------------------
#define FMA2(acc, a, b) \
    asm("fma.rn.f32x2 %0, %1, %2, %0;" : "+l"(acc) : "l"(a), "l"(b))
#define ADD2(acc, a) \
    asm("add.rn.f32x2 %0, %0, %1;" : "+l"(acc) : "l"(a))

__global__ void __launch_bounds__(128, 1)
crf_kernel(const float* __restrict__ emit, const void* __restrict__ mask)
{
    const int lane = threadIdx.x & 31;
    const int wib  = threadIdx.x >> 5;              // warp in block (0..3)
    const int b    = blockIdx.x * 4 + wib;          // batch index (0..1023)

    // Load P into registers (coalesced, L2-resident: 16KB total)
    unsigned long long p[64];
#pragma unroll
    for (int j = 0; j < 64; j++) p[j] = g_P[j * 32 + lane];

    // Sequence length from monotone mask
    const int dt = g_mask_dtype;
    int len = 0;
    if (dt == 0) {
        const unsigned* m = (const unsigned*)mask;  // bytes are exactly 0x00/0x01
        len = __popc(m[b * 64 + lane]) + __popc(m[b * 64 + 32 + lane]);
    } else if (dt == 1) {
        const int* m = (const int*)mask + (size_t)b * TT;
        for (int t = lane; t < TT; t += 32) len += (m[t] != 0);
    } else {
        const float* m = (const float*)mask + (size_t)b * TT;
        for (int t = lane; t < TT; t += 32) len += (m[t] != 0.f);
    }
    len = warp_sum_i(len);

    const float* eb = emit + (size_t)b * TT * NN;

    // alpha0 = strans_n + emit[0]  ->  A0 = Ps * exp(emit0)
    float ax = g_Ps[lane]      * __expf(eb[lane]);
    float ay = g_Ps[lane + 32] * __expf(eb[lane + 32]);
    float C  = 0.f;

    // Broadcast buffer: duplicated pairs (a_j, a_j), 16B-aligned so the inner
    // loop reads two pairs per LDS.128. Double-buffered: one syncwarp/step.
    __shared__ alignas(16) unsigned long long sh[4][2][64];

    int tf = (1 < len) ? 1 : 0;
    float pex = eb[tf * NN + lane];
    float pey = eb[tf * NN + lane + 32];

    for (int t = 1; t < len; t++) {
        const int buf = t & 1;
        sh[wib][buf][lane]      = pack2(ax, ax);
        sh[wib][buf][lane + 32] = pack2(ay, ay);

        // software-pipelined emit prefetch (hides DRAM latency); exp is
        // independent of the FMA chain so it overlaps too.
        const float exe = __expf(pex), eye = __expf(pey);
        const int t2 = (t + 1 < len) ? (t + 1) : t;
        pex = eb[t2 * NN + lane];
        pey = eb[t2 * NN + lane + 32];

        __syncwarp();

        const ulonglong2* sa = (const ulonglong2*)sh[wib][buf];
        unsigned long long acc0 = 0ull, acc1 = 0ull, acc2 = 0ull, acc3 = 0ull;
#pragma unroll
        for (int i = 0; i < 16; i++) {
            ulonglong2 v0 = sa[2 * i];       // pairs j=4i, 4i+1
            ulonglong2 v1 = sa[2 * i + 1];   // pairs j=4i+2, 4i+3
            FMA2(acc0, v0.x, p[4 * i]);
            FMA2(acc1, v0.y, p[4 * i + 1]);
            FMA2(acc2, v1.x, p[4 * i + 2]);
            FMA2(acc3, v1.y, p[4 * i + 3]);
        }
        ADD2(acc0, acc1);
        ADD2(acc2, acc3);
        ADD2(acc0, acc2);
        float sx = __uint_as_float((unsigned)acc0);
        float sy = __uint_as_float((unsigned)(acc0 >> 32));

        ax = sx * exe;
        ay = sy * eye;

        // Renormalize every 8 steps: worst-case growth e^{8*max|emit|} << FLT_MAX
        if ((t & 7) == 0) {
            float s = warp_sum(ax + ay);
            C += __logf(s);
            float inv = __fdividef(1.f, s);
            ax *= inv;
            ay *= inv;
        }
    }

    // logZ_b = C + log(sum_k A_k * exp(etrans_n_k))
    float z = warp_sum(ax * g_Pe[lane] + ay * g_Pe[lane + 32]);
    if (lane == 0) g_logZ[b] = C + __logf(z);
}

// ---------------------------------------------------------------------------
// Deterministic batch reduction (no float atomics).
// ---------------------------------------------------------------------------
__global__ void reduce_kernel(float* __restrict__ out)
{
    __shared__ float s[256];
    int tid = threadIdx.x;
    float v = 0.f;
    for (int i = tid; i < BB; i += 256) v += g_logZ[i];
    s[tid] = v;
    __syncthreads();
    for (int o = 128; o; o >>= 1) {
        if (tid < o) s[tid] += s[tid + o];
        __syncthreads();
    }
    if (tid == 0) out[0] = s[0];
}

extern "C" void kernel_launch(void* const* d_in, const int* in_sizes, int n_in,
                              void* d_out, int out_size)
{
    // Resolve inputs by size (defensive), keeping dict order for the two
    // size-64 vectors (strans before etrans).
    const float* emit   = nullptr;
    const float* trans  = nullptr;
    const float* strans = nullptr;
    const float* etrans = nullptr;
    const void*  mask   = nullptr;
    for (int i = 0; i < n_in; i++) {
        long long sz = in_sizes[i];
        if (sz == (long long)BB * TT * NN)      emit  = (const float*)d_in[i];
        else if (sz == NN * NN)                 trans = (const float*)d_in[i];
        else if (sz == (long long)BB * TT)      mask  = d_in[i];
        else if (sz == NN) {
            if (!strans) strans = (const float*)d_in[i];
            else         etrans = (const float*)d_in[i];
        }
    }

    prep_kernel<<<64, 64>>>(trans, strans, etrans, mask);
    crf_kernel<<<256, 128>>>(emit, mask);
    reduce_kernel<<<1, 256>>>((float*)d_out);
}